// round 13
// baseline (speedup 1.0000x reference)
#include <cuda_runtime.h>

typedef unsigned long long u64;
typedef unsigned int u32;

#define EPSV   1e-3f
#define ALPHAV 0.3f

#define Bn  16
#define Hn  64
#define Wn  64
#define Cn  1024
#define Gn  32
#define CGn 32
#define HT  8
#define WT  32
#define NPOS (HT * WT)             // 256 positions per tile

#define DY_STRIDE 9                // padded stride (float4 units) -> conflict-free
#define DY_F4  (NPOS * DY_STRIDE)  // 2304
#define PW_F4  256
#define ROWF4  272                 // 34 w * 8 c4 (float4 units per interior row)
#define SX_F4  (8 * ROWF4)         // 2176 (interior rows only; halo rows via LDG)
#define SMEM_BYTES ((DY_F4 + PW_F4 + SX_F4) * 16 + 64 * 4)  // 76032 B -> 3 CTAs/SM

__device__ __forceinline__ u64 ffma2(u64 a, u64 b, u64 c) {
    u64 d;
    asm("fma.rn.f32x2 %0, %1, %2, %3;" : "=l"(d) : "l"(a), "l"(b), "l"(c));
    return d;
}
__device__ __forceinline__ u64 pack2(float x, float y) {
    u64 d;
    asm("mov.b64 %0, {%1, %2};" : "=l"(d) : "f"(x), "f"(y));
    return d;
}
__device__ __forceinline__ float2 unpack2(u64 a) {
    float2 r;
    asm("mov.b64 {%0, %1}, %2;" : "=f"(r.x), "=f"(r.y) : "l"(a));
    return r;
}
__device__ __forceinline__ void cp16(u32 dst, const void* src, int sz) {
    asm volatile("cp.async.cg.shared.global [%0], [%1], 16, %2;"
                 :: "r"(dst), "l"(src), "r"(sz));
}
__device__ __forceinline__ u64 lds64(u32 addr) {
    u64 v;
    asm volatile("ld.shared.b64 %0, [%1];" : "=l"(v) : "r"(addr));
    return v;
}
__device__ __forceinline__ void sts64(u32 addr, u64 v) {
    asm volatile("st.shared.b64 [%0], %1;" :: "r"(addr), "l"(v));
}

__global__ __launch_bounds__(256, 3)
void fused_gconv_kernel(const float* __restrict__ x,
                        const float* __restrict__ dwk,
                        const float* __restrict__ pwk,
                        const float* __restrict__ gamma,
                        const float* __restrict__ beta,
                        const float* __restrict__ mmean,
                        const float* __restrict__ mvar,
                        float* __restrict__ out)
{
    extern __shared__ float4 sm4[];
    float4* dy4 = sm4;                      // [256 pos][9] float4 (8 used + 1 pad)
    float4* pw4 = dy4 + DY_F4;              // [32 c][8 d4] float4
    float4* sx4 = pw4 + PW_F4;              // [8 interior rows][34 w][8 c4] float4
    float*  sbs = (float*)(sx4 + SX_F4);    // 32 floats scale
    float*  sbb = sbs + 32;                 // 32 floats bias

    const int g  = blockIdx.x;
    const int ht = blockIdx.y >> 1;
    const int wt = blockIdx.y & 1;
    const int b  = blockIdx.z;
    const int h0 = ht * HT;
    const int w0 = wt * WT;
    const int t  = threadIdx.x;
    const int c0 = g * CGn;

    const u32 sx_s = (u32)__cvta_generic_to_shared(sx4);
    const u32 pw_s = (u32)__cvta_generic_to_shared(pw4);
    const u32 dy_s = (u32)__cvta_generic_to_shared(dy4);

    // ---- async stage: pw weights + interior x rows [8][34][32] (w zfill) ----
    cp16(pw_s + t * 16, pwk + g * CGn * CGn + t * 4, 16);
    {
        const float* xb = x + (u64)b * Hn * Wn * Cn;
        #pragma unroll
        for (int k = 0; k < 9; k++) {
            const int i = t + k * 256;
            if (i < SX_F4) {
                const int row = i / ROWF4;           // 0..7 -> global h0+row
                const int rem = i - row * ROWF4;
                const int w34 = rem >> 3;
                const int cc4 = rem & 7;
                const int wg = w0 - 1 + w34;
                const bool ok = (unsigned)wg < (unsigned)Wn;
                const float* src = ok
                    ? (xb + ((u64)(h0 + row) * Wn + wg) * Cn + c0 + cc4 * 4) : xb;
                cp16(sx_s + i * 16, src, ok ? 16 : 0);
            }
        }
    }
    asm volatile("cp.async.commit_group;");

    // ---- BN scale/bias + dw taps (overlap with cp.async) ----
    if (t < 32) {
        const int c = c0 + t;
        const float s = gamma[c] * rsqrtf(mvar[c] + EPSV);
        sbs[t] = s;
        sbb[t] = beta[c] - mmean[c] * s;
    }
    const int c2 = t & 15;           // channel pair
    u64 kreg[9];
    #pragma unroll
    for (int tap = 0; tap < 9; tap++)
        kreg[tap] = *(const u64*)(dwk + tap * Cn + c0 + c2 * 2);

    // ---- depthwise 3x3: 4 rows x 4 cols x 2 ch per thread ----
    {
        const int wq = (t >> 4) & 7;     // 8 col-quads -> 32 w
        const int rb = t >> 7;           // 0/1 -> output rows rb*4..rb*4+3
        const int hh = rb ? (h0 + 8) : (h0 - 1);          // this patch's halo row
        const bool hok = (unsigned)hh < (unsigned)Hn;
        const float* xhalo = x + ((u64)b * Hn + (hok ? hh : 0)) * Wn * Cn + c0 + c2 * 2;
        const int orow_h = rb ? 3 : 0;   // output row fed by halo
        const int kr_h   = rb ? 2 : 0;   // tap row for halo
        const int sr0    = rb ? 3 : 0;   // first smem row of this patch's window
        const int off    = rb ? 0 : 1;   // window-row offset of smem row 0

        u64 acc[4][4];
        #pragma unroll
        for (int i = 0; i < 4; i++)
            #pragma unroll
            for (int j = 0; j < 4; j++) acc[i][j] = 0ull;

        // 1) batched halo loads (independent -> MLP=6), folded immediately
        {
            u64 hcol[6];
            #pragma unroll
            for (int ci = 0; ci < 6; ci++) {
                const int wg = w0 - 1 + wq * 4 + ci;
                hcol[ci] = (hok && (unsigned)wg < (unsigned)Wn)
                           ? *(const u64*)(xhalo + (u64)wg * Cn) : 0ull;
            }
            #pragma unroll
            for (int ci = 0; ci < 6; ci++) {
                #pragma unroll
                for (int kw = 0; kw < 3; kw++) {
                    const int oc = ci - kw;
                    if (oc >= 0 && oc < 4)
                        acc[orow_h][oc] =
                            ffma2(hcol[ci], kreg[kr_h * 3 + kw], acc[orow_h][oc]);
                }
            }
        }

        asm volatile("cp.async.wait_group 0;" ::: "memory");
        __syncthreads();

        // 2) main loop: pure smem, 5 interior window rows, no bounds checks
        #pragma unroll
        for (int ci = 0; ci < 6; ci++) {
            const int tw = wq * 4 + ci;          // tile col 0..33
            u64 col[5];
            #pragma unroll
            for (int r = 0; r < 5; r++)
                col[r] = lds64(sx_s + ((sr0 + r) * 34 + tw) * 128 + c2 * 8);
            #pragma unroll
            for (int kw = 0; kw < 3; kw++) {
                const int oc = ci - kw;
                if (oc >= 0 && oc < 4) {
                    #pragma unroll
                    for (int r = 0; r < 5; r++) {
                        #pragma unroll
                        for (int kr = 0; kr < 3; kr++) {
                            const int orow = r + off - kr;   // window row = r+off
                            if (orow >= 0 && orow < 4)
                                acc[orow][oc] =
                                    ffma2(col[r], kreg[kr * 3 + kw], acc[orow][oc]);
                        }
                    }
                }
            }
        }

        #pragma unroll
        for (int orow = 0; orow < 4; orow++) {
            #pragma unroll
            for (int oc = 0; oc < 4; oc++) {
                const int pos = (rb * 4 + orow) * WT + wq * 4 + oc;   // 0..255
                sts64(dy_s + pos * (DY_STRIDE * 16) + c2 * 8, acc[orow][oc]);
            }
        }
    }
    __syncthreads();

    // ---- pointwise 32x32 per group + BN + LeakyReLU (8 pos x 4 d / thread) ----
    const int dgroup = t & 7;        // which 4 output channels
    const int d0 = dgroup * 4;
    const int posset = t >> 3;       // 0..31; positions posset + 32*i, i=0..7

    u64 acc[8][2];
    #pragma unroll
    for (int i = 0; i < 8; i++) { acc[i][0] = 0ull; acc[i][1] = 0ull; }

    #pragma unroll
    for (int cq = 0; cq < 8; cq++) {
        float4 dyv[8];
        #pragma unroll
        for (int i = 0; i < 8; i++)
            dyv[i] = dy4[(posset + 32 * i) * DY_STRIDE + cq];
        #pragma unroll
        for (int cc = 0; cc < 4; cc++) {
            const int c = cq * 4 + cc;
            const ulonglong2 pa = *(const ulonglong2*)&pw4[c * 8 + dgroup];
            #pragma unroll
            for (int i = 0; i < 8; i++) {
                const float dc = ((const float*)&dyv[i])[cc];
                const u64 dp = pack2(dc, dc);
                acc[i][0] = ffma2(dp, pa.x, acc[i][0]);
                acc[i][1] = ffma2(dp, pa.y, acc[i][1]);
            }
        }
    }

    // epilogue: BN (one FFMA2 per pair) + LeakyReLU + float4 stores
    const ulonglong2 S  = *(const ulonglong2*)&sbs[d0];
    const ulonglong2 Bb = *(const ulonglong2*)&sbb[d0];
    #pragma unroll
    for (int i = 0; i < 8; i++) {
        const int p = posset + 32 * i;
        const int row = p >> 5, wloc = p & 31;
        const u64 y0 = ffma2(acc[i][0], S.x, Bb.x);
        const u64 y1 = ffma2(acc[i][1], S.y, Bb.y);
        const float2 f0 = unpack2(y0), f1 = unpack2(y1);
        float r[4] = {f0.x, f0.y, f1.x, f1.y};
        #pragma unroll
        for (int k = 0; k < 4; k++)
            r[k] = fmaxf(r[k], 0.f) + ALPHAV * fminf(r[k], 0.f);
        float* op = out + (((u64)b * Hn + h0 + row) * Wn + w0 + wloc) * Cn + c0 + d0;
        *(float4*)op = make_float4(r[0], r[1], r[2], r[3]);
    }
}

extern "C" void kernel_launch(void* const* d_in, const int* in_sizes, int n_in,
                              void* d_out, int out_size)
{
    const float* x     = (const float*)d_in[0];
    const float* dwk   = (const float*)d_in[1];
    const float* pwk   = (const float*)d_in[2];
    const float* gam   = (const float*)d_in[3];
    const float* bet   = (const float*)d_in[4];
    const float* mmean = (const float*)d_in[5];
    const float* mvar  = (const float*)d_in[6];
    float* out = (float*)d_out;

    cudaFuncSetAttribute(fused_gconv_kernel,
                         cudaFuncAttributeMaxDynamicSharedMemorySize, SMEM_BYTES);

    dim3 grid(Gn, (Hn / HT) * (Wn / WT), Bn);   // 32 x 16 x 16 = 8192 blocks
    fused_gconv_kernel<<<grid, 256, SMEM_BYTES>>>(x, dwk, pwk, gam, bet, mmean, mvar, out);
}

// round 14
// speedup vs baseline: 3.4145x; 3.4145x over previous
#include <cuda_runtime.h>

typedef unsigned long long u64;
typedef unsigned int u32;

#define EPSV   1e-3f
#define ALPHAV 0.3f

#define Bn  16
#define Hn  64
#define Wn  64
#define Cn  1024
#define Gn  32
#define CGn 32
#define HT  8
#define WT  32
#define NPOS (HT * WT)             // 256 positions per tile

#define DY_STRIDE 9                // padded stride (float4 units) -> conflict-free
#define DY_F4  (NPOS * DY_STRIDE)  // 2304
#define PW_F4  256
#define ROWF4  272                 // 34 w * 8 c4 (float4 units per interior row)
#define SX_F4  (8 * ROWF4)         // 2176 (interior rows only; halo rows via LDG)
#define SMEM_BYTES ((DY_F4 + PW_F4 + SX_F4) * 16 + 64 * 4)  // 76032 B -> 3 CTAs/SM

template <int V> struct IC { static constexpr int value = V; };

__device__ __forceinline__ u64 ffma2(u64 a, u64 b, u64 c) {
    u64 d;
    asm("fma.rn.f32x2 %0, %1, %2, %3;" : "=l"(d) : "l"(a), "l"(b), "l"(c));
    return d;
}
__device__ __forceinline__ u64 pack2(float x, float y) {
    u64 d;
    asm("mov.b64 %0, {%1, %2};" : "=l"(d) : "f"(x), "f"(y));
    return d;
}
__device__ __forceinline__ float2 unpack2(u64 a) {
    float2 r;
    asm("mov.b64 {%0, %1}, %2;" : "=f"(r.x), "=f"(r.y) : "l"(a));
    return r;
}
__device__ __forceinline__ void cp16(u32 dst, const void* src, int sz) {
    asm volatile("cp.async.cg.shared.global [%0], [%1], 16, %2;"
                 :: "r"(dst), "l"(src), "r"(sz));
}
__device__ __forceinline__ u64 lds64(u32 addr) {
    u64 v;
    asm volatile("ld.shared.b64 %0, [%1];" : "=l"(v) : "r"(addr));
    return v;
}
__device__ __forceinline__ void sts64(u32 addr, u64 v) {
    asm volatile("st.shared.b64 [%0], %1;" :: "r"(addr), "l"(v));
}

__global__ __launch_bounds__(256, 3)
void fused_gconv_kernel(const float* __restrict__ x,
                        const float* __restrict__ dwk,
                        const float* __restrict__ pwk,
                        const float* __restrict__ gamma,
                        const float* __restrict__ beta,
                        const float* __restrict__ mmean,
                        const float* __restrict__ mvar,
                        float* __restrict__ out)
{
    extern __shared__ float4 sm4[];
    float4* dy4 = sm4;                      // [256 pos][9] float4 (8 used + 1 pad)
    float4* pw4 = dy4 + DY_F4;              // [32 c][8 d4] float4
    float4* sx4 = pw4 + PW_F4;              // [8 interior rows][34 w][8 c4] float4
    float*  sbs = (float*)(sx4 + SX_F4);    // 32 floats scale
    float*  sbb = sbs + 32;                 // 32 floats bias

    const int g  = blockIdx.x;
    const int ht = blockIdx.y >> 1;
    const int wt = blockIdx.y & 1;
    const int b  = blockIdx.z;
    const int h0 = ht * HT;
    const int w0 = wt * WT;
    const int t  = threadIdx.x;
    const int c0 = g * CGn;

    const u32 sx_s = (u32)__cvta_generic_to_shared(sx4);
    const u32 pw_s = (u32)__cvta_generic_to_shared(pw4);
    const u32 dy_s = (u32)__cvta_generic_to_shared(dy4);

    // ---- async stage: pw weights + interior x rows [8][34][32] (w zfill) ----
    cp16(pw_s + t * 16, pwk + g * CGn * CGn + t * 4, 16);
    {
        const float* xb = x + (u64)b * Hn * Wn * Cn;
        #pragma unroll
        for (int k = 0; k < 9; k++) {
            const int i = t + k * 256;
            if (i < SX_F4) {
                const int row = i / ROWF4;           // 0..7 -> global h0+row
                const int rem = i - row * ROWF4;
                const int w34 = rem >> 3;
                const int cc4 = rem & 7;
                const int wg = w0 - 1 + w34;
                const bool ok = (unsigned)wg < (unsigned)Wn;
                const float* src = ok
                    ? (xb + ((u64)(h0 + row) * Wn + wg) * Cn + c0 + cc4 * 4) : xb;
                cp16(sx_s + i * 16, src, ok ? 16 : 0);
            }
        }
    }
    asm volatile("cp.async.commit_group;");

    // ---- BN scale/bias + dw taps (overlap with cp.async) ----
    if (t < 32) {
        const int c = c0 + t;
        const float s = gamma[c] * rsqrtf(mvar[c] + EPSV);
        sbs[t] = s;
        sbb[t] = beta[c] - mmean[c] * s;
    }
    const int c2 = t & 15;           // channel pair
    const int wq = (t >> 4) & 7;     // 8 col-quads -> 32 w
    const int rb = t >> 7;           // 0/1 -> output rows rb*4..rb*4+3
    u64 kreg[9];
    #pragma unroll
    for (int tap = 0; tap < 9; tap++)
        kreg[tap] = *(const u64*)(dwk + tap * Cn + c0 + c2 * 2);

    // ---- batched halo loads (before the wait; independent -> MLP=6) ----
    u64 hcol[6];
    {
        const int hh = rb ? (h0 + 8) : (h0 - 1);          // this patch's halo row
        const bool hok = (unsigned)hh < (unsigned)Hn;
        const float* xhalo = x + ((u64)b * Hn + (hok ? hh : 0)) * Wn * Cn
                             + c0 + c2 * 2;
        #pragma unroll
        for (int ci = 0; ci < 6; ci++) {
            const int wg = w0 - 1 + wq * 4 + ci;
            hcol[ci] = (hok && (unsigned)wg < (unsigned)Wn)
                       ? *(const u64*)(xhalo + (u64)wg * Cn) : 0ull;
        }
    }

    asm volatile("cp.async.wait_group 0;" ::: "memory");
    __syncthreads();

    // ---- depthwise 3x3: 4 rows x 4 cols x 2 ch per thread ----
    // RB cloned at compile time -> all acc indices are literals (no spills)
    auto dw_block = [&](auto RBc) {
        constexpr int RB     = decltype(RBc)::value;
        constexpr int orow_h = RB ? 3 : 0;   // output row fed by halo
        constexpr int kr_h   = RB ? 2 : 0;   // tap row for halo
        constexpr int sr0    = RB ? 3 : 0;   // first smem row of this window
        constexpr int off    = RB ? 0 : 1;   // window-row offset of smem row 0

        u64 acc[4][4];
        #pragma unroll
        for (int i = 0; i < 4; i++)
            #pragma unroll
            for (int j = 0; j < 4; j++) acc[i][j] = 0ull;

        // fold the halo row (only output row orow_h, tap row kr_h)
        #pragma unroll
        for (int ci = 0; ci < 6; ci++) {
            #pragma unroll
            for (int kw = 0; kw < 3; kw++) {
                constexpr_if_helper:;
                const int oc = ci - kw;
                if (oc >= 0 && oc < 4)
                    acc[orow_h][oc] =
                        ffma2(hcol[ci], kreg[kr_h * 3 + kw], acc[orow_h][oc]);
            }
        }

        // main loop: pure smem, 5 interior window rows, no bounds checks
        #pragma unroll
        for (int ci = 0; ci < 6; ci++) {
            const int tw = wq * 4 + ci;          // tile col 0..33
            u64 col[5];
            #pragma unroll
            for (int r = 0; r < 5; r++)
                col[r] = lds64(sx_s + ((sr0 + r) * 34 + tw) * 128 + c2 * 8);
            #pragma unroll
            for (int kw = 0; kw < 3; kw++) {
                const int oc = ci - kw;
                if (oc >= 0 && oc < 4) {
                    #pragma unroll
                    for (int r = 0; r < 5; r++) {
                        #pragma unroll
                        for (int kr = 0; kr < 3; kr++) {
                            const int orow = r + off - kr;   // compile-time
                            if (orow >= 0 && orow < 4)
                                acc[orow][oc] =
                                    ffma2(col[r], kreg[kr * 3 + kw], acc[orow][oc]);
                        }
                    }
                }
            }
        }

        #pragma unroll
        for (int orow = 0; orow < 4; orow++) {
            #pragma unroll
            for (int oc = 0; oc < 4; oc++) {
                const int pos = (RB * 4 + orow) * WT + wq * 4 + oc;   // 0..255
                sts64(dy_s + pos * (DY_STRIDE * 16) + c2 * 8, acc[orow][oc]);
            }
        }
    };
    if (rb == 0) dw_block(IC<0>{});
    else         dw_block(IC<1>{});

    __syncthreads();

    // ---- pointwise 32x32 per group + BN + LeakyReLU (8 pos x 4 d / thread) ----
    const int dgroup = t & 7;        // which 4 output channels
    const int d0 = dgroup * 4;
    const int posset = t >> 3;       // 0..31; positions posset + 32*i, i=0..7

    u64 acc[8][2];
    #pragma unroll
    for (int i = 0; i < 8; i++) { acc[i][0] = 0ull; acc[i][1] = 0ull; }

    #pragma unroll
    for (int cq = 0; cq < 8; cq++) {
        float4 dyv[8];
        #pragma unroll
        for (int i = 0; i < 8; i++)
            dyv[i] = dy4[(posset + 32 * i) * DY_STRIDE + cq];
        #pragma unroll
        for (int cc = 0; cc < 4; cc++) {
            const int c = cq * 4 + cc;
            const ulonglong2 pa = *(const ulonglong2*)&pw4[c * 8 + dgroup];
            #pragma unroll
            for (int i = 0; i < 8; i++) {
                const float dc = ((const float*)&dyv[i])[cc];
                const u64 dp = pack2(dc, dc);
                acc[i][0] = ffma2(dp, pa.x, acc[i][0]);
                acc[i][1] = ffma2(dp, pa.y, acc[i][1]);
            }
        }
    }

    // epilogue: BN (one FFMA2 per pair) + LeakyReLU + float4 stores
    const ulonglong2 S  = *(const ulonglong2*)&sbs[d0];
    const ulonglong2 Bb = *(const ulonglong2*)&sbb[d0];
    #pragma unroll
    for (int i = 0; i < 8; i++) {
        const int p = posset + 32 * i;
        const int row = p >> 5, wloc = p & 31;
        const u64 y0 = ffma2(acc[i][0], S.x, Bb.x);
        const u64 y1 = ffma2(acc[i][1], S.y, Bb.y);
        const float2 f0 = unpack2(y0), f1 = unpack2(y1);
        float r[4] = {f0.x, f0.y, f1.x, f1.y};
        #pragma unroll
        for (int k = 0; k < 4; k++)
            r[k] = fmaxf(r[k], 0.f) + ALPHAV * fminf(r[k], 0.f);
        float* op = out + (((u64)b * Hn + h0 + row) * Wn + w0 + wloc) * Cn + c0 + d0;
        *(float4*)op = make_float4(r[0], r[1], r[2], r[3]);
    }
}

extern "C" void kernel_launch(void* const* d_in, const int* in_sizes, int n_in,
                              void* d_out, int out_size)
{
    const float* x     = (const float*)d_in[0];
    const float* dwk   = (const float*)d_in[1];
    const float* pwk   = (const float*)d_in[2];
    const float* gam   = (const float*)d_in[3];
    const float* bet   = (const float*)d_in[4];
    const float* mmean = (const float*)d_in[5];
    const float* mvar  = (const float*)d_in[6];
    float* out = (float*)d_out;

    cudaFuncSetAttribute(fused_gconv_kernel,
                         cudaFuncAttributeMaxDynamicSharedMemorySize, SMEM_BYTES);

    dim3 grid(Gn, (Hn / HT) * (Wn / WT), Bn);   // 32 x 16 x 16 = 8192 blocks
    fused_gconv_kernel<<<grid, 256, SMEM_BYTES>>>(x, dwk, pwk, gam, bet, mmean, mvar, out);
}